// round 6
// baseline (speedup 1.0000x reference)
#include <cuda_runtime.h>

// Problem constants (fixed shapes from the reference)
#define T_  1024
#define B_  2
#define N_  10000
#define L_  30
#define S_  61            // 2*L+1

#define NBLK 1184         // 148 SMs * 8 -> exactly one wave at 8 CTA/SM
#define THR  256
#define STRIDE4 (NBLK * THR)          // 303104 float4 per grid pass (compile-time)
#define TOTAL4  ((T_ * B_ * N_) / 4)  // 5,120,000 float4
#define MASK_BLOCKS 8                 // MASK_BLOCKS*THR == B_*T_ == 2048 masked rows

// Scratch (no allocations allowed -> __device__ globals)
__device__ unsigned long long g_sel[B_][T_];
__device__ unsigned long long g_dup[B_][S_];
__device__ int                g_ext[B_][S_];
__device__ float              g_part[NBLK];
__device__ unsigned int       g_count;

// ---------------------------------------------------------------------------
// Kernel A: build extended labels, dup masks, and the CTC reachability lattice
// (rf & rb) as per-time uint64 bitmasks. One block. Also resets the ticket.
// ---------------------------------------------------------------------------
__global__ void lattice_kernel(const int* __restrict__ label) {
    __shared__ unsigned long long rf[B_][T_];     // 16 KB
    __shared__ unsigned long long rb[B_][T_];     // 16 KB
    __shared__ int fixf[B_], fixb[B_];
    __shared__ unsigned long long cf[B_], cb[B_];

    const int tid = threadIdx.x;
    if (tid == 0) g_count = 0u;   // reset ticket for the fused kernel

    // Phase 0: extended (blank-interleaved) labels
    if (tid < B_ * S_) {
        int b = tid / S_, j = tid % S_;
        g_ext[b][j] = (j & 1) ? label[b * L_ + (j >> 1)] : 0;
    }
    __syncthreads();

    // Phase 1: dup[b][j] = bitmask of j' < j with ext[j'] == ext[j]
    if (tid < B_ * S_) {
        int b = tid / S_, j = tid % S_;
        int v = g_ext[b][j];
        unsigned long long d = 0ull;
        for (int j2 = 0; j2 < j; ++j2)
            if (g_ext[b][j2] == v) d |= 1ull << j2;
        g_dup[b][j] = d;
    }
    __syncthreads();

    // Phase 2: serial bitmask scans (one thread per batch), with fixpoint
    const unsigned long long SMASK = (1ull << S_) - 1ull;
    if (tid < B_) {
        const int b = tid;
        unsigned long long allowF = 0ull, allowB = 0ull;
        int e[S_];
        #pragma unroll
        for (int j = 0; j < S_; ++j) e[j] = g_ext[b][j];
        #pragma unroll
        for (int j = 0; j < S_; ++j) {
            if (e[j] != 0 && (j < 2 || e[j] != e[j - 2]))       allowF |= 1ull << j;
            if (e[j] != 0 && (j >= S_ - 2 || e[j] != e[j + 2])) allowB |= 1ull << j;
        }
        // forward reach: start states {0,1}
        unsigned long long c = 3ull;
        rf[b][0] = c;
        int t = 1;
        for (; t < T_; ++t) {
            unsigned long long n = (c | (c << 1) | ((c << 2) & allowF)) & SMASK;
            if (n == c) break;            // saturated (<= ~60 steps)
            c = n;
            rf[b][t] = c;
        }
        fixf[b] = t; cf[b] = c;

        // backward reach: start states {S-1, S-2}, stored at times T-1 downward
        c = (1ull << (S_ - 1)) | (1ull << (S_ - 2));
        rb[b][T_ - 1] = c;
        int s = 1;
        for (; s < T_; ++s) {
            unsigned long long n = c | (c >> 1) | ((c >> 2) & allowB);
            if (n == c) break;
            c = n;
            rb[b][T_ - 1 - s] = c;
        }
        fixb[b] = s; cb[b] = c;
    }
    __syncthreads();

    // Phase 3: fill the saturated regions in parallel
    for (int b = 0; b < B_; ++b) {
        for (int t = fixf[b] + tid; t < T_; t += blockDim.x)      rf[b][t] = cf[b];
        for (int t = tid; t < T_ - fixb[b]; t += blockDim.x)      rb[b][t] = cb[b];
    }
    __syncthreads();

    // Phase 4: sel = rf & rb -> global
    for (int i = tid; i < B_ * T_; i += blockDim.x) {
        int b = i >> 10, t = i & (T_ - 1);
        g_sel[b][t] = rf[b][t] & rb[b][t];
    }
}

// ---------------------------------------------------------------------------
// Kernel B (fused): full sum of squares (4-way batched LDG.128 for MLP) +
// masked rows folded into the masked blocks' partials + last-block finish.
// Deterministic: fixed accumulation order everywhere.
// ---------------------------------------------------------------------------
__global__ void __launch_bounds__(THR) fused_kernel(const float4* __restrict__ x4,
                                                    const float*  __restrict__ logits,
                                                    float* __restrict__ out) {
    // --- masked rows: blocks 0..MASK_BLOCKS-1, one (b,t) row per thread ---
    float neg = 0.0f;
    if (blockIdx.x < MASK_BLOCKS) {
        const int i = blockIdx.x * THR + threadIdx.x;      // 0..2047
        const int b = i >> 10, t = i & (T_ - 1);
        const unsigned long long sel = g_sel[b][t];
        const float* __restrict__ row = logits + (size_t)t * (B_ * N_) + (size_t)b * N_;
        unsigned long long m = sel;
        while (m) {
            const int j = __ffsll(m) - 1;
            m &= m - 1;
            if ((sel & g_dup[b][j]) == 0ull) {             // dedup repeated vocab ids
                const float v = __ldg(row + g_ext[b][j]);
                neg += v * v;
            }
        }
    }

    // --- full sum of squares: 4 batched independent LDG.128 per iteration ---
    float a0 = 0.0f, a1 = 0.0f, a2 = 0.0f, a3 = 0.0f;
    int i = blockIdx.x * THR + threadIdx.x;
    #pragma unroll 1
    for (; i + 3 * STRIDE4 < TOTAL4; i += 4 * STRIDE4) {
        const float4 v0 = x4[i];
        const float4 v1 = x4[i +     STRIDE4];
        const float4 v2 = x4[i + 2 * STRIDE4];
        const float4 v3 = x4[i + 3 * STRIDE4];
        a0 += v0.x * v0.x + v0.y * v0.y + v0.z * v0.z + v0.w * v0.w;
        a1 += v1.x * v1.x + v1.y * v1.y + v1.z * v1.z + v1.w * v1.w;
        a2 += v2.x * v2.x + v2.y * v2.y + v2.z * v2.z + v2.w * v2.w;
        a3 += v3.x * v3.x + v3.y * v3.y + v3.z * v3.z + v3.w * v3.w;
    }
    for (; i < TOTAL4; i += STRIDE4) {
        const float4 v = x4[i];
        a0 += v.x * v.x + v.y * v.y + v.z * v.z + v.w * v.w;
    }
    const float acc = ((a0 + a1) + (a2 + a3)) - neg;

    __shared__ float sh[THR];
    sh[threadIdx.x] = acc;
    __syncthreads();
    #pragma unroll
    for (int s = THR / 2; s > 0; s >>= 1) {
        if (threadIdx.x < s) sh[threadIdx.x] += sh[threadIdx.x + s];
        __syncthreads();
    }
    if (threadIdx.x == 0) g_part[blockIdx.x] = sh[0];

    // --- last-block finish (threadFenceReduction pattern) ---
    __shared__ bool is_last;
    __threadfence();
    __syncthreads();
    if (threadIdx.x == 0) {
        const unsigned int ticket = atomicAdd(&g_count, 1u);
        is_last = (ticket == gridDim.x - 1);
    }
    __syncthreads();

    if (is_last) {
        float a = 0.0f;
        for (int k = threadIdx.x; k < NBLK; k += THR) a += g_part[k];
        __syncthreads();                // sh reuse barrier
        sh[threadIdx.x] = a;
        __syncthreads();
        #pragma unroll
        for (int s = THR / 2; s > 0; s >>= 1) {
            if (threadIdx.x < s) sh[threadIdx.x] += sh[threadIdx.x + s];
            __syncthreads();
        }
        if (threadIdx.x == 0) out[0] = 0.5f * sh[0];
    }
}

// ---------------------------------------------------------------------------
extern "C" void kernel_launch(void* const* d_in, const int* in_sizes, int n_in,
                              void* d_out, int out_size) {
    // Identify inputs by size (robust to metadata ordering):
    const float* logits = nullptr;
    const int*   label  = nullptr;
    for (int i = 0; i < n_in; ++i) {
        if (in_sizes[i] == T_ * B_ * N_) logits = (const float*)d_in[i];
        else if (in_sizes[i] == B_ * L_) label  = (const int*)d_in[i];
    }
    if (!logits) logits = (const float*)d_in[0];
    if (!label)  label  = (const int*)d_in[2];

    float* out = (float*)d_out;

    lattice_kernel<<<1, 128>>>(label);
    fused_kernel<<<NBLK, THR>>>((const float4*)logits, logits, out);
}

// round 7
// speedup vs baseline: 1.9583x; 1.9583x over previous
#include <cuda_runtime.h>

// Problem constants (fixed shapes from the reference)
#define T_  1024
#define B_  2
#define N_  10000
#define L_  30
#define S_  61            // 2*L+1

#define NBLK 1184         // 148 SMs * 8 -> exactly one wave at 8 CTA/SM
#define THR  256
#define WARPS_PER_BLK (THR / 32)
#define STRIDE4 (NBLK * THR)          // float4 grid stride (compile-time)
#define TOTAL4  ((T_ * B_ * N_) / 4)  // 5,120,000 float4
#define NROWS   (B_ * T_)             // 2048 masked rows -> one warp each

// Scratch (no allocations allowed -> __device__ globals)
__device__ unsigned long long g_sel[B_][T_];
__device__ unsigned long long g_dup[B_][S_];
__device__ int                g_ext[B_][S_];
__device__ float              g_part[NBLK];
__device__ unsigned int       g_count;

// ---------------------------------------------------------------------------
// Kernel A: build extended labels, dup masks, and the CTC reachability lattice
// (rf & rb) as per-time uint64 bitmasks. One block. Also resets the ticket.
// ---------------------------------------------------------------------------
__global__ void lattice_kernel(const int* __restrict__ label) {
    __shared__ unsigned long long rf[B_][T_];     // 16 KB
    __shared__ unsigned long long rb[B_][T_];     // 16 KB
    __shared__ int fixf[B_], fixb[B_];
    __shared__ unsigned long long cf[B_], cb[B_];

    const int tid = threadIdx.x;
    if (tid == 0) g_count = 0u;   // reset ticket for the fused kernel

    // Phase 0: extended (blank-interleaved) labels
    if (tid < B_ * S_) {
        int b = tid / S_, j = tid % S_;
        g_ext[b][j] = (j & 1) ? label[b * L_ + (j >> 1)] : 0;
    }
    __syncthreads();

    // Phase 1: dup[b][j] = bitmask of j' < j with ext[j'] == ext[j]
    if (tid < B_ * S_) {
        int b = tid / S_, j = tid % S_;
        int v = g_ext[b][j];
        unsigned long long d = 0ull;
        for (int j2 = 0; j2 < j; ++j2)
            if (g_ext[b][j2] == v) d |= 1ull << j2;
        g_dup[b][j] = d;
    }
    __syncthreads();

    // Phase 2: serial bitmask scans (one thread per batch), with fixpoint
    const unsigned long long SMASK = (1ull << S_) - 1ull;
    if (tid < B_) {
        const int b = tid;
        unsigned long long allowF = 0ull, allowB = 0ull;
        int e[S_];
        #pragma unroll
        for (int j = 0; j < S_; ++j) e[j] = g_ext[b][j];
        #pragma unroll
        for (int j = 0; j < S_; ++j) {
            if (e[j] != 0 && (j < 2 || e[j] != e[j - 2]))       allowF |= 1ull << j;
            if (e[j] != 0 && (j >= S_ - 2 || e[j] != e[j + 2])) allowB |= 1ull << j;
        }
        // forward reach: start states {0,1}
        unsigned long long c = 3ull;
        rf[b][0] = c;
        int t = 1;
        for (; t < T_; ++t) {
            unsigned long long n = (c | (c << 1) | ((c << 2) & allowF)) & SMASK;
            if (n == c) break;            // saturated (<= ~60 steps)
            c = n;
            rf[b][t] = c;
        }
        fixf[b] = t; cf[b] = c;

        // backward reach: start states {S-1, S-2}, stored at times T-1 downward
        c = (1ull << (S_ - 1)) | (1ull << (S_ - 2));
        rb[b][T_ - 1] = c;
        int s = 1;
        for (; s < T_; ++s) {
            unsigned long long n = c | (c >> 1) | ((c >> 2) & allowB);
            if (n == c) break;
            c = n;
            rb[b][T_ - 1 - s] = c;
        }
        fixb[b] = s; cb[b] = c;
    }
    __syncthreads();

    // Phase 3: fill the saturated regions in parallel
    for (int b = 0; b < B_; ++b) {
        for (int t = fixf[b] + tid; t < T_; t += blockDim.x)      rf[b][t] = cf[b];
        for (int t = tid; t < T_ - fixb[b]; t += blockDim.x)      rb[b][t] = cb[b];
    }
    __syncthreads();

    // Phase 4: sel = rf & rb -> global
    for (int i = tid; i < B_ * T_; i += blockDim.x) {
        int b = i >> 10, t = i & (T_ - 1);
        g_sel[b][t] = rf[b][t] & rb[b][t];
    }
}

// ---------------------------------------------------------------------------
// Kernel B (fused): masked rows (one WARP per row, lane-parallel states) +
// full sum of squares + last-block finish. Deterministic everywhere
// (shuffle/block reductions in fixed order).
// ---------------------------------------------------------------------------
__global__ void __launch_bounds__(THR) fused_kernel(const float4* __restrict__ x4,
                                                    const float*  __restrict__ logits,
                                                    float* __restrict__ out) {
    const int lane = threadIdx.x & 31;
    const int gw   = blockIdx.x * WARPS_PER_BLK + (threadIdx.x >> 5);

    // --- masked rows: warp gw handles row gw; lanes cover states in parallel ---
    float neg = 0.0f;                          // only lane 0 of masked warps holds it
    if (gw < NROWS) {
        const int b = gw >> 10, t = gw & (T_ - 1);
        const unsigned long long sel = g_sel[b][t];
        const float* __restrict__ row = logits + (size_t)t * (B_ * N_) + (size_t)b * N_;

        float s = 0.0f;
        // state j = lane (0..31)
        {
            const int j = lane;
            if ((sel >> j) & 1ull) {
                if ((sel & g_dup[b][j]) == 0ull) {        // first state with this vocab id
                    const float v = __ldg(row + g_ext[b][j]);
                    s += v * v;
                }
            }
        }
        // state j = lane + 32 (32..60)
        {
            const int j = lane + 32;
            if (j < S_ && ((sel >> j) & 1ull)) {
                if ((sel & g_dup[b][j]) == 0ull) {
                    const float v = __ldg(row + g_ext[b][j]);
                    s += v * v;
                }
            }
        }
        // warp reduce (fixed order -> deterministic)
        #pragma unroll
        for (int off = 16; off > 0; off >>= 1)
            s += __shfl_down_sync(0xFFFFFFFFu, s, off);
        if (lane == 0) neg = s;
    }

    // --- full sum of squares: 4 batched independent LDG.128 per iteration ---
    float a0 = 0.0f, a1 = 0.0f, a2 = 0.0f, a3 = 0.0f;
    int i = blockIdx.x * THR + threadIdx.x;
    #pragma unroll 1
    for (; i + 3 * STRIDE4 < TOTAL4; i += 4 * STRIDE4) {
        const float4 v0 = x4[i];
        const float4 v1 = x4[i +     STRIDE4];
        const float4 v2 = x4[i + 2 * STRIDE4];
        const float4 v3 = x4[i + 3 * STRIDE4];
        a0 += v0.x * v0.x + v0.y * v0.y + v0.z * v0.z + v0.w * v0.w;
        a1 += v1.x * v1.x + v1.y * v1.y + v1.z * v1.z + v1.w * v1.w;
        a2 += v2.x * v2.x + v2.y * v2.y + v2.z * v2.z + v2.w * v2.w;
        a3 += v3.x * v3.x + v3.y * v3.y + v3.z * v3.z + v3.w * v3.w;
    }
    for (; i < TOTAL4; i += STRIDE4) {
        const float4 v = x4[i];
        a0 += v.x * v.x + v.y * v.y + v.z * v.z + v.w * v.w;
    }
    const float acc = ((a0 + a1) + (a2 + a3)) - neg;

    __shared__ float sh[THR];
    sh[threadIdx.x] = acc;
    __syncthreads();
    #pragma unroll
    for (int s = THR / 2; s > 0; s >>= 1) {
        if (threadIdx.x < s) sh[threadIdx.x] += sh[threadIdx.x + s];
        __syncthreads();
    }
    if (threadIdx.x == 0) g_part[blockIdx.x] = sh[0];

    // --- last-block finish (threadFenceReduction pattern) ---
    __shared__ bool is_last;
    __threadfence();
    __syncthreads();
    if (threadIdx.x == 0) {
        const unsigned int ticket = atomicAdd(&g_count, 1u);
        is_last = (ticket == gridDim.x - 1);
    }
    __syncthreads();

    if (is_last) {
        float a = 0.0f;
        for (int k = threadIdx.x; k < NBLK; k += THR) a += g_part[k];
        __syncthreads();                // sh reuse barrier
        sh[threadIdx.x] = a;
        __syncthreads();
        #pragma unroll
        for (int s = THR / 2; s > 0; s >>= 1) {
            if (threadIdx.x < s) sh[threadIdx.x] += sh[threadIdx.x + s];
            __syncthreads();
        }
        if (threadIdx.x == 0) out[0] = 0.5f * sh[0];
    }
}

// ---------------------------------------------------------------------------
extern "C" void kernel_launch(void* const* d_in, const int* in_sizes, int n_in,
                              void* d_out, int out_size) {
    // Identify inputs by size (robust to metadata ordering):
    const float* logits = nullptr;
    const int*   label  = nullptr;
    for (int i = 0; i < n_in; ++i) {
        if (in_sizes[i] == T_ * B_ * N_) logits = (const float*)d_in[i];
        else if (in_sizes[i] == B_ * L_) label  = (const int*)d_in[i];
    }
    if (!logits) logits = (const float*)d_in[0];
    if (!label)  label  = (const int*)d_in[2];

    float* out = (float*)d_out;

    lattice_kernel<<<1, 128>>>(label);
    fused_kernel<<<NBLK, THR>>>((const float4*)logits, logits, out);
}

// round 8
// speedup vs baseline: 2.0224x; 1.0327x over previous
#include <cuda_runtime.h>

// Problem constants (fixed shapes from the reference)
#define T_  1024
#define B_  2
#define N_  10000
#define L_  30
#define S_  61            // 2*L+1

#define NBLK 592          // 148 SMs * 4 -> one wave at ~64 regs/thread
#define THR  256
#define WARPS_PER_BLK (THR / 32)
#define STRIDE4 (NBLK * THR)          // 151552 float4 grid stride (compile-time)
#define TOTAL4  ((T_ * B_ * N_) / 4)  // 5,120,000 float4
#define NROWS   (B_ * T_)             // 2048 masked rows -> one warp each

// Scratch (no allocations allowed -> __device__ globals)
__device__ unsigned long long g_sel[B_][T_];
__device__ unsigned long long g_dup[B_][S_];
__device__ int                g_ext[B_][S_];
__device__ float              g_part[NBLK];
__device__ unsigned int       g_count;

// ---------------------------------------------------------------------------
// Kernel A: build extended labels, dup masks, and the CTC reachability lattice
// (rf & rb) as per-time uint64 bitmasks. One block. Also resets the ticket.
// ---------------------------------------------------------------------------
__global__ void lattice_kernel(const int* __restrict__ label) {
    __shared__ unsigned long long rf[B_][T_];     // 16 KB
    __shared__ unsigned long long rb[B_][T_];     // 16 KB
    __shared__ int fixf[B_], fixb[B_];
    __shared__ unsigned long long cf[B_], cb[B_];

    const int tid = threadIdx.x;
    if (tid == 0) g_count = 0u;   // reset ticket for the fused kernel

    // Phase 0: extended (blank-interleaved) labels
    if (tid < B_ * S_) {
        int b = tid / S_, j = tid % S_;
        g_ext[b][j] = (j & 1) ? label[b * L_ + (j >> 1)] : 0;
    }
    __syncthreads();

    // Phase 1: dup[b][j] = bitmask of j' < j with ext[j'] == ext[j]
    if (tid < B_ * S_) {
        int b = tid / S_, j = tid % S_;
        int v = g_ext[b][j];
        unsigned long long d = 0ull;
        for (int j2 = 0; j2 < j; ++j2)
            if (g_ext[b][j2] == v) d |= 1ull << j2;
        g_dup[b][j] = d;
    }
    __syncthreads();

    // Phase 2: serial bitmask scans (one thread per batch), with fixpoint
    const unsigned long long SMASK = (1ull << S_) - 1ull;
    if (tid < B_) {
        const int b = tid;
        unsigned long long allowF = 0ull, allowB = 0ull;
        int e[S_];
        #pragma unroll
        for (int j = 0; j < S_; ++j) e[j] = g_ext[b][j];
        #pragma unroll
        for (int j = 0; j < S_; ++j) {
            if (e[j] != 0 && (j < 2 || e[j] != e[j - 2]))       allowF |= 1ull << j;
            if (e[j] != 0 && (j >= S_ - 2 || e[j] != e[j + 2])) allowB |= 1ull << j;
        }
        // forward reach: start states {0,1}
        unsigned long long c = 3ull;
        rf[b][0] = c;
        int t = 1;
        for (; t < T_; ++t) {
            unsigned long long n = (c | (c << 1) | ((c << 2) & allowF)) & SMASK;
            if (n == c) break;            // saturated (<= ~60 steps)
            c = n;
            rf[b][t] = c;
        }
        fixf[b] = t; cf[b] = c;

        // backward reach: start states {S-1, S-2}, stored at times T-1 downward
        c = (1ull << (S_ - 1)) | (1ull << (S_ - 2));
        rb[b][T_ - 1] = c;
        int s = 1;
        for (; s < T_; ++s) {
            unsigned long long n = c | (c >> 1) | ((c >> 2) & allowB);
            if (n == c) break;
            c = n;
            rb[b][T_ - 1 - s] = c;
        }
        fixb[b] = s; cb[b] = c;
    }
    __syncthreads();

    // Phase 3: fill the saturated regions in parallel
    for (int b = 0; b < B_; ++b) {
        for (int t = fixf[b] + tid; t < T_; t += blockDim.x)      rf[b][t] = cf[b];
        for (int t = tid; t < T_ - fixb[b]; t += blockDim.x)      rb[b][t] = cb[b];
    }
    __syncthreads();

    // Phase 4: sel = rf & rb -> global
    for (int i = tid; i < B_ * T_; i += blockDim.x) {
        int b = i >> 10, t = i & (T_ - 1);
        g_sel[b][t] = rf[b][t] & rb[b][t];
    }
}

// ---------------------------------------------------------------------------
// Kernel B (fused): masked rows (one WARP per row, lane-parallel states) +
// full sum of squares with 8 batched independent LDG.128 per iteration +
// last-block finish. Deterministic everywhere (fixed-order reductions).
// ---------------------------------------------------------------------------
__global__ void __launch_bounds__(THR, 4) fused_kernel(const float4* __restrict__ x4,
                                                       const float*  __restrict__ logits,
                                                       float* __restrict__ out) {
    const int lane = threadIdx.x & 31;
    const int gw   = blockIdx.x * WARPS_PER_BLK + (threadIdx.x >> 5);

    // --- masked rows: warp gw handles row gw; lanes cover states in parallel ---
    float neg = 0.0f;                          // only lane 0 of masked warps holds it
    if (gw < NROWS) {
        const int b = gw >> 10, t = gw & (T_ - 1);
        const unsigned long long sel = g_sel[b][t];
        const float* __restrict__ row = logits + (size_t)t * (B_ * N_) + (size_t)b * N_;

        float s = 0.0f;
        {   // state j = lane (0..31)
            const int j = lane;
            if (((sel >> j) & 1ull) && (sel & g_dup[b][j]) == 0ull) {
                const float v = __ldg(row + g_ext[b][j]);
                s += v * v;
            }
        }
        {   // state j = lane + 32 (32..60)
            const int j = lane + 32;
            if (j < S_ && ((sel >> j) & 1ull) && (sel & g_dup[b][j]) == 0ull) {
                const float v = __ldg(row + g_ext[b][j]);
                s += v * v;
            }
        }
        #pragma unroll
        for (int off = 16; off > 0; off >>= 1)
            s += __shfl_down_sync(0xFFFFFFFFu, s, off);
        if (lane == 0) neg = s;
    }

    // --- full sum of squares: 8 batched independent LDG.128 per iteration ---
    float a0 = 0.f, a1 = 0.f, a2 = 0.f, a3 = 0.f,
          a4 = 0.f, a5 = 0.f, a6 = 0.f, a7 = 0.f;
    int i = blockIdx.x * THR + threadIdx.x;
    #pragma unroll 1
    for (; i + 7 * STRIDE4 < TOTAL4; i += 8 * STRIDE4) {
        const float4 v0 = x4[i];
        const float4 v1 = x4[i +     STRIDE4];
        const float4 v2 = x4[i + 2 * STRIDE4];
        const float4 v3 = x4[i + 3 * STRIDE4];
        const float4 v4 = x4[i + 4 * STRIDE4];
        const float4 v5 = x4[i + 5 * STRIDE4];
        const float4 v6 = x4[i + 6 * STRIDE4];
        const float4 v7 = x4[i + 7 * STRIDE4];
        a0 += v0.x * v0.x + v0.y * v0.y + v0.z * v0.z + v0.w * v0.w;
        a1 += v1.x * v1.x + v1.y * v1.y + v1.z * v1.z + v1.w * v1.w;
        a2 += v2.x * v2.x + v2.y * v2.y + v2.z * v2.z + v2.w * v2.w;
        a3 += v3.x * v3.x + v3.y * v3.y + v3.z * v3.z + v3.w * v3.w;
        a4 += v4.x * v4.x + v4.y * v4.y + v4.z * v4.z + v4.w * v4.w;
        a5 += v5.x * v5.x + v5.y * v5.y + v5.z * v5.z + v5.w * v5.w;
        a6 += v6.x * v6.x + v6.y * v6.y + v6.z * v6.z + v6.w * v6.w;
        a7 += v7.x * v7.x + v7.y * v7.y + v7.z * v7.z + v7.w * v7.w;
    }
    for (; i < TOTAL4; i += STRIDE4) {
        const float4 v = x4[i];
        a0 += v.x * v.x + v.y * v.y + v.z * v.z + v.w * v.w;
    }
    const float acc = (((a0 + a1) + (a2 + a3)) + ((a4 + a5) + (a6 + a7))) - neg;

    __shared__ float sh[THR];
    sh[threadIdx.x] = acc;
    __syncthreads();
    #pragma unroll
    for (int s = THR / 2; s > 0; s >>= 1) {
        if (threadIdx.x < s) sh[threadIdx.x] += sh[threadIdx.x + s];
        __syncthreads();
    }
    if (threadIdx.x == 0) g_part[blockIdx.x] = sh[0];

    // --- last-block finish (threadFenceReduction pattern) ---
    __shared__ bool is_last;
    __threadfence();
    __syncthreads();
    if (threadIdx.x == 0) {
        const unsigned int ticket = atomicAdd(&g_count, 1u);
        is_last = (ticket == gridDim.x - 1);
    }
    __syncthreads();

    if (is_last) {
        float a = 0.0f;
        for (int k = threadIdx.x; k < NBLK; k += THR) a += g_part[k];
        __syncthreads();                // sh reuse barrier
        sh[threadIdx.x] = a;
        __syncthreads();
        #pragma unroll
        for (int s = THR / 2; s > 0; s >>= 1) {
            if (threadIdx.x < s) sh[threadIdx.x] += sh[threadIdx.x + s];
            __syncthreads();
        }
        if (threadIdx.x == 0) out[0] = 0.5f * sh[0];
    }
}

// ---------------------------------------------------------------------------
extern "C" void kernel_launch(void* const* d_in, const int* in_sizes, int n_in,
                              void* d_out, int out_size) {
    // Identify inputs by size (robust to metadata ordering):
    const float* logits = nullptr;
    const int*   label  = nullptr;
    for (int i = 0; i < n_in; ++i) {
        if (in_sizes[i] == T_ * B_ * N_) logits = (const float*)d_in[i];
        else if (in_sizes[i] == B_ * L_) label  = (const int*)d_in[i];
    }
    if (!logits) logits = (const float*)d_in[0];
    if (!label)  label  = (const int*)d_in[2];

    float* out = (float*)d_out;

    lattice_kernel<<<1, 128>>>(label);
    fused_kernel<<<NBLK, THR>>>((const float4*)logits, logits, out);
}

// round 9
// speedup vs baseline: 2.4894x; 1.2309x over previous
#include <cuda_runtime.h>

// Problem constants (fixed shapes from the reference)
#define T_  1024
#define B_  2
#define N_  10000
#define L_  30
#define S_  61            // 2*L+1

#define NBLK 592          // 148 SMs * 4 -> one wave at ~64 regs/thread
#define THR  256
#define WPB  (THR / 32)               // 8 warps per block
#define STRIDE4 (NBLK * THR)          // float4 grid stride (compile-time)
#define TOTAL4  ((T_ * B_ * N_) / 4)  // 5,120,000 float4
#define NROWS   (B_ * T_)             // 2048 masked rows -> one warp each
#define MASK_BLK (NROWS / WPB)        // 256 masked blocks

// Scratch (no allocations allowed -> __device__ globals)
__device__ float        g_part[NBLK];
__device__ unsigned int g_count;      // zero-init; advances by exactly NBLK per launch

// ---------------------------------------------------------------------------
// Single fused kernel:
//  - per-masked-block smem setup: ext labels, dup masks, lattice BFS distances
//    (closed form: state j active at time t  <=>  d_f[j] <= t && d_b[j] <= T-1-t)
//  - full sum of squares, 8 batched independent LDG.128 per iteration
//  - warp-per-row masked gather (post-stream, warm L2)
//  - deterministic last-block finish (ticket modulo NBLK -> graph-replay safe)
// ---------------------------------------------------------------------------
__global__ void __launch_bounds__(THR, 4) fused_kernel(const float4* __restrict__ x4,
                                                       const float*  __restrict__ logits,
                                                       const int*    __restrict__ label,
                                                       float* __restrict__ out) {
    const int tid  = threadIdx.x;
    const int lane = tid & 31;
    const int wid  = tid >> 5;
    const bool masked_blk = (blockIdx.x < MASK_BLK);

    __shared__ int                s_ext[S_];
    __shared__ unsigned long long s_dup[S_];
    __shared__ short              s_df[S_], s_db[S_];
    __shared__ float              sh[THR];

    // all 8 rows of a masked block share one batch (1024 rows/batch, 8 rows/block)
    const int bb = (int)((blockIdx.x * WPB) >> 10);

    // --- Phase 0: extended (blank-interleaved) labels ---
    if (masked_blk && tid < S_)
        s_ext[tid] = (tid & 1) ? label[bb * L_ + (tid >> 1)] : 0;
    __syncthreads();

    // --- Phase 1: dup masks + forward/backward BFS distances ---
    if (masked_blk) {
        if (tid < S_) {
            const int v = s_ext[tid];
            unsigned long long d = 0ull;
            for (int j2 = 0; j2 < tid; ++j2)
                if (s_ext[j2] == v) d |= 1ull << j2;
            s_dup[tid] = d;
        }
        if (tid == 64) {           // d_f: serial 61-step relaxation (warp 2)
            int dm2 = 0, dm1 = 0;  // d_f[j-2], d_f[j-1]
            s_df[0] = 0; s_df[1] = 0;
            for (int j = 2; j < S_; ++j) {
                int best = dm1;
                if (s_ext[j] != 0 && s_ext[j] != s_ext[j - 2] && dm2 < best) best = dm2;
                const int d = best + 1;
                s_df[j] = (short)d;
                dm2 = dm1; dm1 = d;
            }
        }
        if (tid == 96) {           // d_b: serial 61-step relaxation (warp 3)
            int dp2 = 0, dp1 = 0;  // d_b[j+2], d_b[j+1]
            s_db[S_ - 1] = 0; s_db[S_ - 2] = 0;
            for (int j = S_ - 3; j >= 0; --j) {
                int best = dp1;
                if (s_ext[j] != 0 && s_ext[j] != s_ext[j + 2] && dp2 < best) best = dp2;
                const int d = best + 1;
                s_db[j] = (short)d;
                dp2 = dp1; dp1 = d;
            }
        }
    }

    // --- full sum of squares: 8 batched independent LDG.128 per iteration ---
    float a0 = 0.f, a1 = 0.f, a2 = 0.f, a3 = 0.f,
          a4 = 0.f, a5 = 0.f, a6 = 0.f, a7 = 0.f;
    int i = blockIdx.x * THR + tid;
    #pragma unroll 1
    for (; i + 7 * STRIDE4 < TOTAL4; i += 8 * STRIDE4) {
        const float4 v0 = x4[i];
        const float4 v1 = x4[i +     STRIDE4];
        const float4 v2 = x4[i + 2 * STRIDE4];
        const float4 v3 = x4[i + 3 * STRIDE4];
        const float4 v4 = x4[i + 4 * STRIDE4];
        const float4 v5 = x4[i + 5 * STRIDE4];
        const float4 v6 = x4[i + 6 * STRIDE4];
        const float4 v7 = x4[i + 7 * STRIDE4];
        a0 += v0.x * v0.x + v0.y * v0.y + v0.z * v0.z + v0.w * v0.w;
        a1 += v1.x * v1.x + v1.y * v1.y + v1.z * v1.z + v1.w * v1.w;
        a2 += v2.x * v2.x + v2.y * v2.y + v2.z * v2.z + v2.w * v2.w;
        a3 += v3.x * v3.x + v3.y * v3.y + v3.z * v3.z + v3.w * v3.w;
        a4 += v4.x * v4.x + v4.y * v4.y + v4.z * v4.z + v4.w * v4.w;
        a5 += v5.x * v5.x + v5.y * v5.y + v5.z * v5.z + v5.w * v5.w;
        a6 += v6.x * v6.x + v6.y * v6.y + v6.z * v6.z + v6.w * v6.w;
        a7 += v7.x * v7.x + v7.y * v7.y + v7.z * v7.z + v7.w * v7.w;
    }
    for (; i < TOTAL4; i += STRIDE4) {
        const float4 v = x4[i];
        a0 += v.x * v.x + v.y * v.y + v.z * v.z + v.w * v.w;
    }
    float acc = (((a0 + a1) + (a2 + a3)) + ((a4 + a5) + (a6 + a7)));

    __syncthreads();   // phase-1 smem writes -> visible to gather readers

    // --- masked rows: warp-per-row gather, lane-parallel states (warm L2) ---
    float neg = 0.0f;
    if (masked_blk) {
        const int gw = blockIdx.x * WPB + wid;   // row id 0..2047
        const int t  = gw & (T_ - 1);
        const int bt = T_ - 1 - t;
        const float* __restrict__ row = logits + (size_t)t * (B_ * N_) + (size_t)bb * N_;

        const int  j1   = lane + 32;
        const bool act0 = (s_df[lane] <= t) && (s_db[lane] <= bt);
        const bool act1 = (j1 < S_) && (s_df[j1] <= t) && (s_db[j1] <= bt);
        const unsigned lo = __ballot_sync(0xFFFFFFFFu, act0);
        const unsigned hi = __ballot_sync(0xFFFFFFFFu, act1);
        const unsigned long long sel =
            (unsigned long long)lo | ((unsigned long long)hi << 32);

        float s = 0.0f;
        if (act0 && (sel & s_dup[lane]) == 0ull) {
            const float v = __ldg(row + s_ext[lane]);
            s += v * v;
        }
        if (act1 && (sel & s_dup[j1]) == 0ull) {
            const float v = __ldg(row + s_ext[j1]);
            s += v * v;
        }
        #pragma unroll
        for (int off = 16; off > 0; off >>= 1)
            s += __shfl_down_sync(0xFFFFFFFFu, s, off);
        if (lane == 0) neg = s;
    }

    // --- block reduce (fixed order -> deterministic) ---
    sh[tid] = acc - neg;
    __syncthreads();
    #pragma unroll
    for (int s = THR / 2; s > 0; s >>= 1) {
        if (tid < s) sh[tid] += sh[tid + s];
        __syncthreads();
    }
    if (tid == 0) g_part[blockIdx.x] = sh[0];

    // --- last-block finish; ticket advances by exactly NBLK per launch ---
    __shared__ bool is_last;
    __threadfence();
    __syncthreads();
    if (tid == 0) {
        const unsigned int ticket = atomicAdd(&g_count, 1u);
        is_last = ((ticket + 1u) % (unsigned)NBLK == 0u);
    }
    __syncthreads();

    if (is_last) {
        float a = 0.0f;
        for (int k = tid; k < NBLK; k += THR) a += g_part[k];
        __syncthreads();                // sh reuse barrier
        sh[tid] = a;
        __syncthreads();
        #pragma unroll
        for (int s = THR / 2; s > 0; s >>= 1) {
            if (tid < s) sh[tid] += sh[tid + s];
            __syncthreads();
        }
        if (tid == 0) out[0] = 0.5f * sh[0];
    }
}

// ---------------------------------------------------------------------------
extern "C" void kernel_launch(void* const* d_in, const int* in_sizes, int n_in,
                              void* d_out, int out_size) {
    // Identify inputs by size (robust to metadata ordering):
    const float* logits = nullptr;
    const int*   label  = nullptr;
    for (int i = 0; i < n_in; ++i) {
        if (in_sizes[i] == T_ * B_ * N_) logits = (const float*)d_in[i];
        else if (in_sizes[i] == B_ * L_) label  = (const int*)d_in[i];
    }
    if (!logits) logits = (const float*)d_in[0];
    if (!label)  label  = (const int*)d_in[2];

    float* out = (float*)d_out;

    fused_kernel<<<NBLK, THR>>>((const float4*)logits, logits, label, out);
}

// round 10
// speedup vs baseline: 2.8799x; 1.1569x over previous
#include <cuda_runtime.h>

// Problem constants (fixed shapes from the reference)
#define T_  1024
#define B_  2
#define N_  10000
#define L_  30
#define S_  61            // 2*L+1

#define NBLK 592          // 148 SMs * 4 -> one wave at ~56 regs/thread
#define THR  256
#define WPB  (THR / 32)               // 8 warps per block
#define STRIDE4 (NBLK * THR)          // 151552 float4 grid stride (compile-time)
#define TOTAL4  ((T_ * B_ * N_) / 4)  // 5,120,000 float4
#define NROWS   (B_ * T_)             // 2048 masked rows -> one warp each
#define MASK_BLK (NROWS / WPB)        // 256 masked blocks
#define FULL_ITERS 4                  // 4 x 8 x STRIDE4 = 4,849,664 <= TOTAL4
#define REM_BASE (FULL_ITERS * 8 * STRIDE4)   // 4,849,664; leftover 270,336 < 2*STRIDE4

// Scratch (no allocations allowed -> __device__ globals)
__device__ float        g_part[NBLK];
__device__ unsigned int g_count;      // zero-init; advances by exactly NBLK per launch

// ---------------------------------------------------------------------------
// Single fused kernel:
//  - masked-block smem setup: ext labels, dup masks, lattice BFS distances
//    computed register-resident (state j active at t <=> d_f[j]<=t && d_b[j]<=T-1-t)
//  - full sum of squares: 4 compile-time iterations of 8 batched LDG.128 +
//    2 batched predicated remainder loads (every thread has 1 or 2)
//  - warp-per-row masked gather (post-stream, warm L2)
//  - deterministic last-block finish (ticket modulo NBLK -> graph-replay safe)
// ---------------------------------------------------------------------------
__global__ void __launch_bounds__(THR, 4) fused_kernel(const float4* __restrict__ x4,
                                                       const float*  __restrict__ logits,
                                                       const int*    __restrict__ label,
                                                       float* __restrict__ out) {
    const int tid  = threadIdx.x;
    const int lane = tid & 31;
    const int wid  = tid >> 5;
    const bool masked_blk = (blockIdx.x < MASK_BLK);

    __shared__ int                s_ext[S_];
    __shared__ unsigned long long s_dup[S_];
    __shared__ short              s_df[S_], s_db[S_];
    __shared__ float              sh[THR];

    // all 8 rows of a masked block share one batch (1024 rows/batch, 8 rows/block)
    const int bb = (int)((blockIdx.x * WPB) >> 10);

    // --- Phase 0: extended (blank-interleaved) labels ---
    if (masked_blk && tid < S_)
        s_ext[tid] = (tid & 1) ? label[bb * L_ + (tid >> 1)] : 0;
    __syncthreads();

    // --- Phase 1: dup masks + forward/backward BFS distances (reg-resident) ---
    if (masked_blk) {
        if (tid < S_) {
            const int v = s_ext[tid];
            unsigned long long d = 0ull;
            for (int j2 = 0; j2 < tid; ++j2)
                if (s_ext[j2] == v) d |= 1ull << j2;
            s_dup[tid] = d;
        }
        if (tid == 64) {                 // d_f in registers (warp 2)
            int e[S_];
            #pragma unroll
            for (int j = 0; j < S_; ++j) e[j] = s_ext[j];
            short df[S_];
            df[0] = 0; df[1] = 0;
            int dm2 = 0, dm1 = 0;
            #pragma unroll
            for (int j = 2; j < S_; ++j) {
                int best = dm1;
                if (e[j] != 0 && e[j] != e[j - 2] && dm2 < best) best = dm2;
                const int d = best + 1;
                df[j] = (short)d;
                dm2 = dm1; dm1 = d;
            }
            #pragma unroll
            for (int j = 0; j < S_; ++j) s_df[j] = df[j];
        }
        if (tid == 96) {                 // d_b in registers (warp 3)
            int e[S_];
            #pragma unroll
            for (int j = 0; j < S_; ++j) e[j] = s_ext[j];
            short db[S_];
            db[S_ - 1] = 0; db[S_ - 2] = 0;
            int dp2 = 0, dp1 = 0;
            #pragma unroll
            for (int j = S_ - 3; j >= 0; --j) {
                int best = dp1;
                if (e[j] != 0 && e[j] != e[j + 2] && dp2 < best) best = dp2;
                const int d = best + 1;
                db[j] = (short)d;
                dp2 = dp1; dp1 = d;
            }
            #pragma unroll
            for (int j = 0; j < S_; ++j) s_db[j] = db[j];
        }
    }

    // --- full sum of squares: 4 x (8 batched LDG.128), compile-time bounds ---
    const int gid = blockIdx.x * THR + tid;
    float a0 = 0.f, a1 = 0.f, a2 = 0.f, a3 = 0.f,
          a4 = 0.f, a5 = 0.f, a6 = 0.f, a7 = 0.f;
    #pragma unroll 1
    for (int it = 0; it < FULL_ITERS; ++it) {
        const int i = gid + it * (8 * STRIDE4);
        const float4 v0 = x4[i];
        const float4 v1 = x4[i +     STRIDE4];
        const float4 v2 = x4[i + 2 * STRIDE4];
        const float4 v3 = x4[i + 3 * STRIDE4];
        const float4 v4 = x4[i + 4 * STRIDE4];
        const float4 v5 = x4[i + 5 * STRIDE4];
        const float4 v6 = x4[i + 6 * STRIDE4];
        const float4 v7 = x4[i + 7 * STRIDE4];
        a0 += v0.x * v0.x + v0.y * v0.y + v0.z * v0.z + v0.w * v0.w;
        a1 += v1.x * v1.x + v1.y * v1.y + v1.z * v1.z + v1.w * v1.w;
        a2 += v2.x * v2.x + v2.y * v2.y + v2.z * v2.z + v2.w * v2.w;
        a3 += v3.x * v3.x + v3.y * v3.y + v3.z * v3.z + v3.w * v3.w;
        a4 += v4.x * v4.x + v4.y * v4.y + v4.z * v4.z + v4.w * v4.w;
        a5 += v5.x * v5.x + v5.y * v5.y + v5.z * v5.z + v5.w * v5.w;
        a6 += v6.x * v6.x + v6.y * v6.y + v6.z * v6.z + v6.w * v6.w;
        a7 += v7.x * v7.x + v7.y * v7.y + v7.z * v7.z + v7.w * v7.w;
    }
    // remainder: every thread has exactly 1 or 2 elements -> 2 batched loads
    {
        const int r0 = REM_BASE + gid;            // always < TOTAL4
        const int r1 = r0 + STRIDE4;
        const float4 v0 = x4[r0];
        a0 += v0.x * v0.x + v0.y * v0.y + v0.z * v0.z + v0.w * v0.w;
        if (r1 < TOTAL4) {
            const float4 v1 = x4[r1];
            a1 += v1.x * v1.x + v1.y * v1.y + v1.z * v1.z + v1.w * v1.w;
        }
    }
    float acc = (((a0 + a1) + (a2 + a3)) + ((a4 + a5) + (a6 + a7)));

    __syncthreads();   // phase-1 smem writes -> visible to gather readers

    // --- masked rows: warp-per-row gather, lane-parallel states (warm L2) ---
    float neg = 0.0f;
    if (masked_blk) {
        const int gw = blockIdx.x * WPB + wid;   // row id 0..2047
        const int t  = gw & (T_ - 1);
        const int bt = T_ - 1 - t;
        const float* __restrict__ row = logits + (size_t)t * (B_ * N_) + (size_t)bb * N_;

        const int  j1   = lane + 32;
        const bool act0 = (s_df[lane] <= t) && (s_db[lane] <= bt);
        const bool act1 = (j1 < S_) && (s_df[j1] <= t) && (s_db[j1] <= bt);
        const unsigned lo = __ballot_sync(0xFFFFFFFFu, act0);
        const unsigned hi = __ballot_sync(0xFFFFFFFFu, act1);
        const unsigned long long sel =
            (unsigned long long)lo | ((unsigned long long)hi << 32);

        float s = 0.0f;
        if (act0 && (sel & s_dup[lane]) == 0ull) {
            const float v = __ldg(row + s_ext[lane]);
            s += v * v;
        }
        if (act1 && (sel & s_dup[j1]) == 0ull) {
            const float v = __ldg(row + s_ext[j1]);
            s += v * v;
        }
        #pragma unroll
        for (int off = 16; off > 0; off >>= 1)
            s += __shfl_down_sync(0xFFFFFFFFu, s, off);
        if (lane == 0) neg = s;
    }

    // --- block reduce (fixed order -> deterministic) ---
    sh[tid] = acc - neg;
    __syncthreads();
    #pragma unroll
    for (int s = THR / 2; s > 0; s >>= 1) {
        if (tid < s) sh[tid] += sh[tid + s];
        __syncthreads();
    }
    if (tid == 0) g_part[blockIdx.x] = sh[0];

    // --- last-block finish; ticket advances by exactly NBLK per launch ---
    __shared__ bool is_last;
    __threadfence();
    __syncthreads();
    if (tid == 0) {
        const unsigned int ticket = atomicAdd(&g_count, 1u);
        is_last = ((ticket + 1u) % (unsigned)NBLK == 0u);
    }
    __syncthreads();

    if (is_last) {
        float a = 0.0f;
        for (int k = tid; k < NBLK; k += THR) a += g_part[k];
        __syncthreads();                // sh reuse barrier
        sh[tid] = a;
        __syncthreads();
        #pragma unroll
        for (int s = THR / 2; s > 0; s >>= 1) {
            if (tid < s) sh[tid] += sh[tid + s];
            __syncthreads();
        }
        if (tid == 0) out[0] = 0.5f * sh[0];
    }
}

// ---------------------------------------------------------------------------
extern "C" void kernel_launch(void* const* d_in, const int* in_sizes, int n_in,
                              void* d_out, int out_size) {
    // Identify inputs by size (robust to metadata ordering):
    const float* logits = nullptr;
    const int*   label  = nullptr;
    for (int i = 0; i < n_in; ++i) {
        if (in_sizes[i] == T_ * B_ * N_) logits = (const float*)d_in[i];
        else if (in_sizes[i] == B_ * L_) label  = (const int*)d_in[i];
    }
    if (!logits) logits = (const float*)d_in[0];
    if (!label)  label  = (const int*)d_in[2];

    float* out = (float*)d_out;

    fused_kernel<<<NBLK, THR>>>((const float4*)logits, logits, label, out);
}